// round 14
// baseline (speedup 1.0000x reference)
#include <cuda_runtime.h>
#include <cstdint>

#define T_LEN   16384
#define T_MASK  16383
#define L_HALF  50
#define NMN     449
#define NK      11
#define NOUT    16284      // T - 2*L
#define TILE_T  256
#define THREADS 256
#define CHUNK   64

typedef unsigned long long u64;

// -------- compile-time (m,n) pair table (reference enumeration order) --------
struct MNTab { short m[NMN]; short n[NMN]; };
constexpr MNTab make_mn() {
    MNTab t{};
    int c = 0;
    for (int m = -25; m <= 25; ++m)
        for (int n = -25; n <= 25; ++n) {
            int p = m * n; if (p < 0) p = -p;
            if (p <= 25) { t.m[c] = (short)m; t.n[c] = (short)n; ++c; }
        }
    return t;
}
__constant__ MNTab c_mn = make_mn();

// -------- packed f32x2 helpers (Blackwell FFMA2) --------
static __device__ __forceinline__ u64 f2fma(u64 a, u64 b, u64 c) {
    u64 d; asm("fma.rn.f32x2 %0, %1, %2, %3;" : "=l"(d) : "l"(a), "l"(b), "l"(c)); return d;
}
static __device__ __forceinline__ u64 f2mul(u64 a, u64 b) {
    u64 d; asm("mul.rn.f32x2 %0, %1, %2;" : "=l"(d) : "l"(a), "l"(b)); return d;
}
static __device__ __forceinline__ u64 pk2(float lo, float hi) {
    u64 d; asm("mov.b64 %0, {%1, %2};" : "=l"(d) : "f"(lo), "f"(hi)); return d;
}
static __device__ __forceinline__ float2 up2(u64 v) {
    float2 r; asm("mov.b64 {%0, %1}, %2;" : "=f"(r.x), "=f"(r.y) : "l"(v)); return r;
}
static __device__ __forceinline__ u64 ng2(u64 v) { return v ^ 0x8000000080000000ULL; }

// -------- single fused kernel --------
// grid = (64 t-tiles, 2 batches); 256 threads.
//   warps 0-3 (g=0): A, cp-acc, G1 (A*C1), final store
//   warps 4-7 (g=1): A, G2 (conj(A)*C2), partial via smem
// Each thread covers t1 = win0+slot, t2 = win0+slot+128 (f32x2-packed ILP2).
// Coefficients are scaled (f3/f5) and laid out (dual FFMA2 form) on the fly
// during smem staging, reading raw L2-resident inputs — no pack kernel.
__global__ __launch_bounds__(THREADS)
void sopbc_fused(const float* __restrict__ Er,   const float* __restrict__ Ei,
                 const float* __restrict__ ti,
                 const float* __restrict__ pbcr, const float* __restrict__ pbci,
                 const float* __restrict__ c1r,  const float* __restrict__ c1i,
                 const float* __restrict__ c2r,  const float* __restrict__ c2i,
                 float* __restrict__ out) {
    __shared__ float2 sE[356];
    __shared__ float4 s_cf[CHUNK * 23];
    __shared__ float4 s_red[128];

    const int tid  = threadIdx.x;
    const int slot = tid & 127;
    const int g    = tid >> 7;
    const int b    = blockIdx.y;
    const int base = b * T_LEN;
    const int win0 = blockIdx.x * TILE_T;

    // per-block coefficient parameters (cheap, every thread computes)
    const int xi = (int)(ti[b * 4 + 2] / 2.0e9f);
    int ind = 0;
    if (xi == 40) ind = 1;
    else if (xi == 80) ind = 2;
    else if (xi == 160) ind = 3;
    const float P  = exp10f(ti[b * 4 + 0] * 0.1f);
    const float sp = sqrtf(P);
    const float f3 = sp * sp * sp;
    const float f5 = f3 * sp * sp;
    const int cbase = ind * (NMN * NK);

    for (int i = tid; i < 356; i += THREADS) {
        int t = (win0 + i) & T_MASK;
        sE[i] = make_float2(Er[base + t], Ei[base + t]);
    }

    u64 X[NK], Y[NK];
    u64 A0 = 0ull, A1 = 0ull;
#pragma unroll
    for (int j = 0; j < NK; ++j) { X[j] = Y[j] = 0ull; }

    const int i1 = slot + L_HALF;
    const int i2 = slot + 128 + L_HALF;

    for (int p0 = 0; p0 < NMN; p0 += CHUNK) {
        const int np = (NMN - p0 < CHUNK) ? (NMN - p0) : CHUNK;
        __syncthreads();
        // stage + scale + dual-layout coefficients for this chunk
        {
            const int cnt = np * 23;
            for (int i = tid; i < cnt; i += THREADS) {
                int p  = i / 23;
                int j  = i - p * 23;
                int gp = p0 + p;
                float4 v;
                if (j == 0) {
                    float cr = f3 * pbcr[ind * NMN + gp];
                    float ci = f3 * pbci[ind * NMN + gp];
                    v = make_float4(cr, ci, -ci, cr);
                } else if (j < 12) {
                    int o = cbase + gp * NK + (j - 1);
                    float u = f5 * c1r[o], w = f5 * c1i[o];
                    v = make_float4(u, w, -w, u);         // A * C1
                } else {
                    int o = cbase + gp * NK + (j - 12);
                    float u = f5 * c2r[o], w = f5 * c2i[o];
                    v = make_float4(u, w, w, -u);         // conj(A) * C2
                }
                s_cf[i] = v;
            }
        }
        __syncthreads();

        if (g == 0) {
            for (int p = 0; p < np; ++p) {
                const int m = c_mn.m[p0 + p], n = c_mn.n[p0 + p];
                float2 av1 = sE[i1 - n],     av2 = sE[i2 - n];
                float2 bv1 = sE[i1 - m - n], bv2 = sE[i2 - m - n];
                float2 cv1 = sE[i1 - m],     cv2 = sE[i2 - m];

                u64 ar = pk2(av1.x, av2.x), ai = pk2(av1.y, av2.y);
                u64 br = pk2(bv1.x, bv2.x), bi = pk2(bv1.y, bv2.y);
                u64 cr = pk2(cv1.x, cv2.x), ci = pk2(cv1.y, cv2.y);

                u64 ur  = f2fma(ai, bi, f2mul(ar, br));
                u64 ui  = f2fma(ai, br, f2mul(ng2(ar), bi));
                u64 Arr = f2fma(ng2(ui), ci, f2mul(ur, cr));
                u64 Aii = f2fma(ur, ci, f2mul(ui, cr));

                float2 arp = up2(Arr), aip = up2(Aii);
                u64 R1 = pk2(arp.x, arp.x), I1 = pk2(aip.x, aip.x);
                u64 R2 = pk2(arp.y, arp.y), I2 = pk2(aip.y, aip.y);

                const ulonglong2* cf = reinterpret_cast<const ulonglong2*>(s_cf + p * 23);
                ulonglong2 c0 = cf[0];
                A0 = f2fma(I1, c0.y, f2fma(R1, c0.x, A0));
                A1 = f2fma(I2, c0.y, f2fma(R2, c0.x, A1));
#pragma unroll
                for (int j = 0; j < NK; ++j) {
                    ulonglong2 c = cf[1 + j];
                    X[j] = f2fma(I1, c.y, f2fma(R1, c.x, X[j]));
                    Y[j] = f2fma(I2, c.y, f2fma(R2, c.x, Y[j]));
                }
            }
        } else {
            for (int p = 0; p < np; ++p) {
                const int m = c_mn.m[p0 + p], n = c_mn.n[p0 + p];
                float2 av1 = sE[i1 - n],     av2 = sE[i2 - n];
                float2 bv1 = sE[i1 - m - n], bv2 = sE[i2 - m - n];
                float2 cv1 = sE[i1 - m],     cv2 = sE[i2 - m];

                u64 ar = pk2(av1.x, av2.x), ai = pk2(av1.y, av2.y);
                u64 br = pk2(bv1.x, bv2.x), bi = pk2(bv1.y, bv2.y);
                u64 cr = pk2(cv1.x, cv2.x), ci = pk2(cv1.y, cv2.y);

                u64 ur  = f2fma(ai, bi, f2mul(ar, br));
                u64 ui  = f2fma(ai, br, f2mul(ng2(ar), bi));
                u64 Arr = f2fma(ng2(ui), ci, f2mul(ur, cr));
                u64 Aii = f2fma(ur, ci, f2mul(ui, cr));

                float2 arp = up2(Arr), aip = up2(Aii);
                u64 R1 = pk2(arp.x, arp.x), I1 = pk2(aip.x, aip.x);
                u64 R2 = pk2(arp.y, arp.y), I2 = pk2(aip.y, aip.y);

                const ulonglong2* cf = reinterpret_cast<const ulonglong2*>(s_cf + p * 23);
#pragma unroll
                for (int j = 0; j < NK; ++j) {
                    ulonglong2 c = cf[12 + j];
                    X[j] = f2fma(I1, c.y, f2fma(R1, c.x, X[j]));
                    Y[j] = f2fma(I2, c.y, f2fma(R2, c.x, Y[j]));
                }
            }
        }
    }

    // ---- epilogue ----
    if (g == 1) {
        // partial: sum_j Q * G2  (Q = E^2 at t-k)
        float pr1 = 0.f, pi1 = 0.f, pr2 = 0.f, pi2 = 0.f;
#pragma unroll
        for (int j = 0; j < NK; ++j) {
            float2 e1 = sE[i1 + 5 - j];
            float Qr1 = e1.x * e1.x - e1.y * e1.y;
            float Qi1 = 2.f * e1.x * e1.y;
            float2 g2 = up2(X[j]);
            pr1 += Qr1 * g2.x - Qi1 * g2.y;
            pi1 += Qr1 * g2.y + Qi1 * g2.x;

            float2 e2 = sE[i2 + 5 - j];
            float Qr2 = e2.x * e2.x - e2.y * e2.y;
            float Qi2 = 2.f * e2.x * e2.y;
            float2 h2 = up2(Y[j]);
            pr2 += Qr2 * h2.x - Qi2 * h2.y;
            pi2 += Qr2 * h2.y + Qi2 * h2.x;
        }
        s_red[slot] = make_float4(pr1, pi1, pr2, pi2);
    }
    __syncthreads();
    if (g == 0) {
        float4 r = s_red[slot];
        // t1 (always valid: max to1 = 63*256+127 = 16255 < 16284)
        {
            float2 e0 = sE[i1];
            float2 cp = up2(A0);
            float er = e0.x + cp.x + r.x, eim = e0.y + cp.y + r.y;
#pragma unroll
            for (int j = 0; j < NK; ++j) {
                float2 e  = sE[i1 + 5 - j];
                float Iv  = e.x * e.x + e.y * e.y;
                float2 g1 = up2(X[j]);
                er  += Iv * g1.x;
                eim += Iv * g1.y;
            }
            int to = win0 + slot;
            out[(b * NOUT + to) * 2 + 0] = er;
            out[(b * NOUT + to) * 2 + 1] = eim;
        }
        // t2 (guarded)
        {
            int to = win0 + slot + 128;
            if (to < NOUT) {
                float2 e0 = sE[i2];
                float2 cp = up2(A1);
                float er = e0.x + cp.x + r.z, eim = e0.y + cp.y + r.w;
#pragma unroll
                for (int j = 0; j < NK; ++j) {
                    float2 e  = sE[i2 + 5 - j];
                    float Iv  = e.x * e.x + e.y * e.y;
                    float2 g1 = up2(Y[j]);
                    er  += Iv * g1.x;
                    eim += Iv * g1.y;
                }
                out[(b * NOUT + to) * 2 + 0] = er;
                out[(b * NOUT + to) * 2 + 1] = eim;
            }
        }
    }
}

extern "C" void kernel_launch(void* const* d_in, const int* in_sizes, int n_in,
                              void* d_out, int out_size) {
    const float* Er   = (const float*)d_in[0];
    const float* Ei   = (const float*)d_in[1];
    const float* ti   = (const float*)d_in[2];
    const float* pbcr = (const float*)d_in[3];
    const float* pbci = (const float*)d_in[4];
    const float* c1r  = (const float*)d_in[5];
    const float* c1i  = (const float*)d_in[6];
    const float* c2r  = (const float*)d_in[7];
    const float* c2i  = (const float*)d_in[8];
    float* out = (float*)d_out;

    dim3 grid(64, 2);
    sopbc_fused<<<grid, THREADS>>>(Er, Ei, ti, pbcr, pbci, c1r, c1i, c2r, c2i, out);
}